// round 1
// baseline (speedup 1.0000x reference)
#include <cuda_runtime.h>
#include <math.h>
#include <math_constants.h>

// Problem constants
#define BQ 2
#define LQ 2048
#define DQ 1024
#define HQ 16
#define HDQ 64
#define MQ (BQ*LQ)          // 4096 rows
#define SSZ ((size_t)MQ*DQ) // elements per [B,L,D] buffer

// Scratch: Qr,Qi,Kr,Ki,Vr,Vi,Or,Oi  (8 x 16MB fp32)
__device__ float g_buf[8*SSZ];

// ---------------------------------------------------------------------------
// Complex linear: out[m,n] (+i) = sum_k (xr+ i xi)[m,k] * (wr + i wi)[n,k]
//   outr = xr@wr^T - xi@wi^T ; outi = xr@wi^T + xi@wr^T
// M=4096, N=1024, K=1024, all row-major, K contiguous (NT GEMM).
// Tile 64x64, BK=16, 256 threads, each thread 4x4 per output (strided map).
// ---------------------------------------------------------------------------
__global__ __launch_bounds__(256, 2)
void clinear_kernel(const float* __restrict__ xr, const float* __restrict__ xi,
                    const float* __restrict__ wr, const float* __restrict__ wi,
                    float* __restrict__ outr, float* __restrict__ outi,
                    const float* __restrict__ br, const float* __restrict__ bi)
{
    __shared__ float As_r[64*17], As_i[64*17], Bs_r[64*17], Bs_i[64*17];

    const int m0 = blockIdx.x * 64;
    const int n0 = blockIdx.y * 64;
    const int tid = threadIdx.x;
    const int tx = tid & 15, ty = tid >> 4;

    // loader mapping: one float4 per tensor per k-step
    const int lrow = tid >> 2;        // 0..63
    const int lk   = (tid & 3) * 4;   // 0,4,8,12

    const float* pa_r = xr + (size_t)(m0 + lrow) * DQ + lk;
    const float* pa_i = xi + (size_t)(m0 + lrow) * DQ + lk;
    const float* pb_r = wr + (size_t)(n0 + lrow) * DQ + lk;
    const float* pb_i = wi + (size_t)(n0 + lrow) * DQ + lk;

    float accr[4][4] = {}, acci[4][4] = {};

    for (int k0 = 0; k0 < DQ; k0 += 16) {
        const float4 ar4 = *(const float4*)(pa_r + k0);
        const float4 ai4 = *(const float4*)(pa_i + k0);
        const float4 br4 = *(const float4*)(pb_r + k0);
        const float4 bi4 = *(const float4*)(pb_i + k0);
        __syncthreads();   // previous iteration's reads done
        As_r[lrow*17 + lk + 0] = ar4.x; As_r[lrow*17 + lk + 1] = ar4.y;
        As_r[lrow*17 + lk + 2] = ar4.z; As_r[lrow*17 + lk + 3] = ar4.w;
        As_i[lrow*17 + lk + 0] = ai4.x; As_i[lrow*17 + lk + 1] = ai4.y;
        As_i[lrow*17 + lk + 2] = ai4.z; As_i[lrow*17 + lk + 3] = ai4.w;
        Bs_r[lrow*17 + lk + 0] = br4.x; Bs_r[lrow*17 + lk + 1] = br4.y;
        Bs_r[lrow*17 + lk + 2] = br4.z; Bs_r[lrow*17 + lk + 3] = br4.w;
        Bs_i[lrow*17 + lk + 0] = bi4.x; Bs_i[lrow*17 + lk + 1] = bi4.y;
        Bs_i[lrow*17 + lk + 2] = bi4.z; Bs_i[lrow*17 + lk + 3] = bi4.w;
        __syncthreads();

        #pragma unroll
        for (int kk = 0; kk < 16; kk++) {
            float a_r[4], a_i[4], b_r[4], b_i[4];
            #pragma unroll
            for (int i = 0; i < 4; i++) {
                a_r[i] = As_r[(ty + 16*i)*17 + kk];   // broadcast across tx
                a_i[i] = As_i[(ty + 16*i)*17 + kk];
            }
            #pragma unroll
            for (int j = 0; j < 4; j++) {
                b_r[j] = Bs_r[(tx + 16*j)*17 + kk];   // stride-17: conflict free
                b_i[j] = Bs_i[(tx + 16*j)*17 + kk];
            }
            #pragma unroll
            for (int i = 0; i < 4; i++)
                #pragma unroll
                for (int j = 0; j < 4; j++) {
                    accr[i][j] = fmaf(a_r[i], b_r[j], accr[i][j]);
                    accr[i][j] = fmaf(-a_i[i], b_i[j], accr[i][j]);
                    acci[i][j] = fmaf(a_r[i], b_i[j], acci[i][j]);
                    acci[i][j] = fmaf(a_i[i], b_r[j], acci[i][j]);
                }
        }
    }

    const bool hb = (br != nullptr);
    #pragma unroll
    for (int i = 0; i < 4; i++) {
        const int mrow = m0 + ty + 16*i;
        #pragma unroll
        for (int j = 0; j < 4; j++) {
            const int ncol = n0 + tx + 16*j;
            float vr = accr[i][j], vi = acci[i][j];
            if (hb) { vr += br[ncol]; vi += bi[ncol]; }
            outr[(size_t)mrow*DQ + ncol] = vr;
            outi[(size_t)mrow*DQ + ncol] = vi;
        }
    }
}

// ---------------------------------------------------------------------------
// Flash attention, causal, complex scores: S = (Qr Kr^T + Qi Ki^T) * 0.125
// One block per (q-tile of 64, head, batch). 256 threads (16x16), each thread
// owns rows {ty+16i} and cols {tx+16j} (strided -> bank-friendly LDS).
// ---------------------------------------------------------------------------
#define LDK 68
#define FLASH_SMEM ((6*64*LDK + 64*64) * 4)

__device__ __forceinline__ float redmax16(float v) {
    v = fmaxf(v, __shfl_xor_sync(0xffffffffu, v, 1));
    v = fmaxf(v, __shfl_xor_sync(0xffffffffu, v, 2));
    v = fmaxf(v, __shfl_xor_sync(0xffffffffu, v, 4));
    v = fmaxf(v, __shfl_xor_sync(0xffffffffu, v, 8));
    return v;
}
__device__ __forceinline__ float redsum16(float v) {
    v += __shfl_xor_sync(0xffffffffu, v, 1);
    v += __shfl_xor_sync(0xffffffffu, v, 2);
    v += __shfl_xor_sync(0xffffffffu, v, 4);
    v += __shfl_xor_sync(0xffffffffu, v, 8);
    return v;
}

__global__ __launch_bounds__(256, 1)
void flash_kernel(const float* __restrict__ Qr, const float* __restrict__ Qi,
                  const float* __restrict__ Kr, const float* __restrict__ Ki,
                  const float* __restrict__ Vr, const float* __restrict__ Vi,
                  float* __restrict__ Or_, float* __restrict__ Oi_)
{
    extern __shared__ float sm[];
    float* Qs_r = sm;
    float* Qs_i = Qs_r + 64*LDK;
    float* Ks_r = Qs_i + 64*LDK;
    float* Ks_i = Ks_r + 64*LDK;
    float* Vt_r = Ks_i + 64*LDK;   // transposed: [dv][k]
    float* Vt_i = Vt_r + 64*LDK;
    float* Ps   = Vt_i + 64*LDK;   // [64][64]

    const int qt = blockIdx.x;
    const int h  = blockIdx.y;
    const int b  = blockIdx.z;
    const int q0 = qt * 64;
    const int tid = threadIdx.x;
    const int tx = tid & 15, ty = tid >> 4;
    const size_t base = ((size_t)b * LQ) * DQ + (size_t)h * HDQ;

    const int lrow = tid >> 4;          // 0..15
    const int fc   = (tid & 15) * 4;    // 0..60

    // Load Q tile (rows q0..q0+63, 64 head dims), natural layout
    #pragma unroll
    for (int r4 = 0; r4 < 4; r4++) {
        const int row = lrow + 16*r4;
        const float4 qr = *(const float4*)(Qr + base + (size_t)(q0+row)*DQ + fc);
        const float4 qi = *(const float4*)(Qi + base + (size_t)(q0+row)*DQ + fc);
        *(float4*)&Qs_r[row*LDK + fc] = qr;
        *(float4*)&Qs_i[row*LDK + fc] = qi;
    }

    float m_i[4], l_i[4];
    float o_r[4][4], o_i[4][4];
    #pragma unroll
    for (int i = 0; i < 4; i++) {
        m_i[i] = -CUDART_INF_F; l_i[i] = 0.f;
        #pragma unroll
        for (int j = 0; j < 4; j++) { o_r[i][j] = 0.f; o_i[i][j] = 0.f; }
    }

    for (int kt = 0; kt <= qt; kt++) {
        const int k0 = kt * 64;
        __syncthreads();   // previous tile fully consumed
        #pragma unroll
        for (int r4 = 0; r4 < 4; r4++) {
            const int row = lrow + 16*r4;
            const float4 kr = *(const float4*)(Kr + base + (size_t)(k0+row)*DQ + fc);
            const float4 ki = *(const float4*)(Ki + base + (size_t)(k0+row)*DQ + fc);
            *(float4*)&Ks_r[row*LDK + fc] = kr;
            *(float4*)&Ks_i[row*LDK + fc] = ki;
            const float4 vr = *(const float4*)(Vr + base + (size_t)(k0+row)*DQ + fc);
            const float4 vi = *(const float4*)(Vi + base + (size_t)(k0+row)*DQ + fc);
            Vt_r[(fc+0)*LDK + row] = vr.x; Vt_r[(fc+1)*LDK + row] = vr.y;
            Vt_r[(fc+2)*LDK + row] = vr.z; Vt_r[(fc+3)*LDK + row] = vr.w;
            Vt_i[(fc+0)*LDK + row] = vi.x; Vt_i[(fc+1)*LDK + row] = vi.y;
            Vt_i[(fc+2)*LDK + row] = vi.z; Vt_i[(fc+3)*LDK + row] = vi.w;
        }
        __syncthreads();

        // --- S = Qr Kr^T + Qi Ki^T over 64 dims ---
        float s_[4][4] = {};
        #pragma unroll
        for (int d4 = 0; d4 < 64; d4 += 4) {
            float4 q_r[4], q_i[4];
            #pragma unroll
            for (int i = 0; i < 4; i++) {
                q_r[i] = *(const float4*)&Qs_r[(ty + 16*i)*LDK + d4];
                q_i[i] = *(const float4*)&Qs_i[(ty + 16*i)*LDK + d4];
            }
            #pragma unroll
            for (int j = 0; j < 4; j++) {
                const float4 k_r = *(const float4*)&Ks_r[(tx + 16*j)*LDK + d4];
                const float4 k_i = *(const float4*)&Ks_i[(tx + 16*j)*LDK + d4];
                #pragma unroll
                for (int i = 0; i < 4; i++) {
                    float acc = s_[i][j];
                    acc = fmaf(q_r[i].x, k_r.x, acc);
                    acc = fmaf(q_r[i].y, k_r.y, acc);
                    acc = fmaf(q_r[i].z, k_r.z, acc);
                    acc = fmaf(q_r[i].w, k_r.w, acc);
                    acc = fmaf(q_i[i].x, k_i.x, acc);
                    acc = fmaf(q_i[i].y, k_i.y, acc);
                    acc = fmaf(q_i[i].z, k_i.z, acc);
                    acc = fmaf(q_i[i].w, k_i.w, acc);
                    s_[i][j] = acc;
                }
            }
        }

        // --- online softmax update ---
        const bool diag = (kt == qt);
        #pragma unroll
        for (int i = 0; i < 4; i++) {
            const int qrow = ty + 16*i;
            float rm = -CUDART_INF_F;
            #pragma unroll
            for (int j = 0; j < 4; j++) {
                float v = s_[i][j] * 0.125f;
                if (diag && (tx + 16*j) > qrow) v = -CUDART_INF_F;
                s_[i][j] = v;
                rm = fmaxf(rm, v);
            }
            rm = redmax16(rm);
            const float mnew = fmaxf(m_i[i], rm);
            const float corr = __expf(m_i[i] - mnew);
            m_i[i] = mnew;
            float rs = 0.f;
            #pragma unroll
            for (int j = 0; j < 4; j++) {
                const float p = __expf(s_[i][j] - mnew);
                Ps[qrow*64 + tx + 16*j] = p;
                rs += p;
            }
            rs = redsum16(rs);
            l_i[i] = l_i[i]*corr + rs;
            #pragma unroll
            for (int j = 0; j < 4; j++) { o_r[i][j] *= corr; o_i[i][j] *= corr; }
        }
        __syncthreads();   // P visible to all

        // --- O += P @ V (r and i) over 64 keys ---
        #pragma unroll
        for (int k4 = 0; k4 < 64; k4 += 4) {
            float4 p4[4];
            #pragma unroll
            for (int i = 0; i < 4; i++)
                p4[i] = *(const float4*)&Ps[(ty + 16*i)*64 + k4];
            #pragma unroll
            for (int j = 0; j < 4; j++) {
                const float4 v_r = *(const float4*)&Vt_r[(tx + 16*j)*LDK + k4];
                const float4 v_i = *(const float4*)&Vt_i[(tx + 16*j)*LDK + k4];
                #pragma unroll
                for (int i = 0; i < 4; i++) {
                    float ar = o_r[i][j], ai = o_i[i][j];
                    ar = fmaf(p4[i].x, v_r.x, ar); ai = fmaf(p4[i].x, v_i.x, ai);
                    ar = fmaf(p4[i].y, v_r.y, ar); ai = fmaf(p4[i].y, v_i.y, ai);
                    ar = fmaf(p4[i].z, v_r.z, ar); ai = fmaf(p4[i].z, v_i.z, ai);
                    ar = fmaf(p4[i].w, v_r.w, ar); ai = fmaf(p4[i].w, v_i.w, ai);
                    o_r[i][j] = ar; o_i[i][j] = ai;
                }
            }
        }
    }

    // normalize and write merged [B,L,D]
    #pragma unroll
    for (int i = 0; i < 4; i++) {
        const float inv = 1.0f / l_i[i];
        const int qrow = q0 + ty + 16*i;
        #pragma unroll
        for (int j = 0; j < 4; j++) {
            const size_t idx = base + (size_t)qrow*DQ + tx + 16*j;
            Or_[idx] = o_r[i][j] * inv;
            Oi_[idx] = o_i[i][j] * inv;
        }
    }
}

// ---------------------------------------------------------------------------
extern "C" void kernel_launch(void* const* d_in, const int* in_sizes, int n_in,
                              void* d_out, int out_size)
{
    const float* x_r  = (const float*)d_in[0];
    const float* x_i  = (const float*)d_in[1];
    const float* wq_r = (const float*)d_in[2];
    const float* wq_i = (const float*)d_in[3];
    const float* wk_r = (const float*)d_in[4];
    const float* wk_i = (const float*)d_in[5];
    const float* wv_r = (const float*)d_in[6];
    const float* wv_i = (const float*)d_in[7];
    const float* wo_r = (const float*)d_in[8];
    const float* wo_i = (const float*)d_in[9];
    const float* bo_r = (const float*)d_in[10];
    const float* bo_i = (const float*)d_in[11];

    float* scratch = nullptr;
    cudaGetSymbolAddress((void**)&scratch, g_buf);
    float* Qr = scratch + 0*SSZ;
    float* Qi = scratch + 1*SSZ;
    float* Kr = scratch + 2*SSZ;
    float* Ki = scratch + 3*SSZ;
    float* Vr = scratch + 4*SSZ;
    float* Vi = scratch + 5*SSZ;
    float* Or_ = scratch + 6*SSZ;
    float* Oi_ = scratch + 7*SSZ;

    float* yr = (float*)d_out;
    float* yi = yr + SSZ;

    cudaFuncSetAttribute(flash_kernel,
                         cudaFuncAttributeMaxDynamicSharedMemorySize, FLASH_SMEM);

    dim3 gl(MQ/64, DQ/64, 1);   // 64 x 16
    clinear_kernel<<<gl, 256>>>(x_r, x_i, wq_r, wq_i, Qr, Qi, nullptr, nullptr);
    clinear_kernel<<<gl, 256>>>(x_r, x_i, wk_r, wk_i, Kr, Ki, nullptr, nullptr);
    clinear_kernel<<<gl, 256>>>(x_r, x_i, wv_r, wv_i, Vr, Vi, nullptr, nullptr);

    dim3 gf(LQ/64, HQ, BQ);     // 32 x 16 x 2
    flash_kernel<<<gf, 256, FLASH_SMEM>>>(Qr, Qi, Kr, Ki, Vr, Vi, Or_, Oi_);

    clinear_kernel<<<gl, 256>>>(Or_, Oi_, wo_r, wo_i, yr, yi, bo_r, bo_i);
}

// round 2
// speedup vs baseline: 1.4565x; 1.4565x over previous
#include <cuda_runtime.h>
#include <cuda_bf16.h>
#include <math.h>
#include <math_constants.h>
#include <stdint.h>

// Problem constants
#define BQ 2
#define LQ 2048
#define DQ 1024
#define HQ 16
#define HDQ 64
#define MQ (BQ*LQ)          // 4096 rows
#define SSZ ((size_t)MQ*DQ) // elements per [B,L,D] buffer
#define GK 6144             // concat K: [hi_r|hi_i|hi_r|hi_i|lo_r|lo_i] x 1024

// fp32 scratch: Qr,Qi,Kr,Ki,Vr,Vi,Or,Oi
__device__ float g_buf[8*SSZ];                       // 128 MB
// bf16 split operands
__device__ __nv_bfloat16 g_Ax[(size_t)MQ*GK];        // 48 MB
__device__ __nv_bfloat16 g_Bqkv[(size_t)6*1024*GK];  // 72 MB
__device__ __nv_bfloat16 g_Ao[(size_t)MQ*GK];        // 48 MB
__device__ __nv_bfloat16 g_Bo[(size_t)2*1024*GK];    // 24 MB

// ---------------------------------------------------------------------------
// Split-prep kernels
// A row m, cols: [k]=hi(xr) [1024+k]=hi(xi) [2048+k]=hi(xr) [3072+k]=hi(xi)
//                [4096+k]=lo(xr) [5120+k]=lo(xi)
// ---------------------------------------------------------------------------
__global__ void build_A_kernel(const float* __restrict__ xr,
                               const float* __restrict__ xi,
                               __nv_bfloat16* __restrict__ A)
{
    const int idx = blockIdx.x * blockDim.x + threadIdx.x;
    if (idx >= MQ*DQ) return;
    const int m = idx >> 10, k = idx & 1023;
    const float vr = xr[idx], vi = xi[idx];
    const __nv_bfloat16 hr = __float2bfloat16(vr);
    const __nv_bfloat16 lr = __float2bfloat16(vr - __bfloat162float(hr));
    const __nv_bfloat16 hi_ = __float2bfloat16(vi);
    const __nv_bfloat16 li_ = __float2bfloat16(vi - __bfloat162float(hi_));
    __nv_bfloat16* row = A + (size_t)m * GK;
    row[k]        = hr;
    row[1024 + k] = hi_;
    row[2048 + k] = hr;
    row[3072 + k] = hi_;
    row[4096 + k] = lr;
    row[5120 + k] = li_;
}

// B rows for one complex weight (wr, wi):
//  r-row n:      [hi(wr) | hi(-wi) | lo(wr) | lo(-wi) | hi(wr) | hi(-wi)]
//  i-row n+1024: [hi(wi) | hi(wr)  | lo(wi) | lo(wr)  | hi(wi) | hi(wr) ]
// dot(A_row, B_r_row) = full (xr*wr - xi*wi) minus negligible lo*lo term.
__global__ void build_B_kernel(const float* __restrict__ wr,
                               const float* __restrict__ wi,
                               __nv_bfloat16* __restrict__ Bdst)
{
    const int idx = blockIdx.x * blockDim.x + threadIdx.x;
    if (idx >= DQ*DQ) return;
    const int n = idx >> 10, k = idx & 1023;
    const float vr = wr[idx], vi = wi[idx];
    const __nv_bfloat16 hr  = __float2bfloat16(vr);
    const __nv_bfloat16 lr  = __float2bfloat16(vr - __bfloat162float(hr));
    const __nv_bfloat16 hi_ = __float2bfloat16(vi);
    const __nv_bfloat16 li_ = __float2bfloat16(vi - __bfloat162float(hi_));
    const float nvi = -vi;
    const __nv_bfloat16 hni = __float2bfloat16(nvi);
    const __nv_bfloat16 lni = __float2bfloat16(nvi - __bfloat162float(hni));

    __nv_bfloat16* rrow = Bdst + (size_t)n * GK;
    __nv_bfloat16* irow = Bdst + (size_t)(n + 1024) * GK;
    rrow[k]        = hr;
    rrow[1024 + k] = hni;
    rrow[2048 + k] = lr;
    rrow[3072 + k] = lni;
    rrow[4096 + k] = hr;
    rrow[5120 + k] = hni;

    irow[k]        = hi_;
    irow[1024 + k] = hr;
    irow[2048 + k] = li_;
    irow[3072 + k] = lr;
    irow[4096 + k] = hi_;
    irow[5120 + k] = hr;
}

// ---------------------------------------------------------------------------
// bf16 tensor-core GEMM: out[m,n] = sum_k A[m,k] * B[n,k]   (NT, K-major both)
// M=4096 fixed, N = gridDim.x*128, K = GK.
// 256 threads, 8 warps (2M x 4N), warp tile 64x32, mma.m16n8k16, double-buffered.
// Output mapping: out[(n>>10)*SSZ + m*1024 + (n&1023)]  (+ optional bias)
// ---------------------------------------------------------------------------
#define GBM 128
#define GBN 128
#define GBK 32
#define GLDA 40   // padded row stride (elements) -> 80B rows, LDSM conflict-free

__device__ __forceinline__ void ldsm_x4(uint32_t& r0, uint32_t& r1,
                                        uint32_t& r2, uint32_t& r3, uint32_t addr)
{
    asm volatile("ldmatrix.sync.aligned.m8n8.x4.shared.b16 {%0,%1,%2,%3}, [%4];"
                 : "=r"(r0), "=r"(r1), "=r"(r2), "=r"(r3) : "r"(addr));
}

__device__ __forceinline__ void mma_bf16(float* c,
                                         uint32_t a0, uint32_t a1, uint32_t a2, uint32_t a3,
                                         uint32_t b0, uint32_t b1)
{
    asm volatile("mma.sync.aligned.m16n8k16.row.col.f32.bf16.bf16.f32 "
                 "{%0,%1,%2,%3},{%4,%5,%6,%7},{%8,%9},{%0,%1,%2,%3};"
                 : "+f"(c[0]), "+f"(c[1]), "+f"(c[2]), "+f"(c[3])
                 : "r"(a0), "r"(a1), "r"(a2), "r"(a3), "r"(b0), "r"(b1));
}

__global__ __launch_bounds__(256, 1)
void gemm_bf16(const __nv_bfloat16* __restrict__ A,
               const __nv_bfloat16* __restrict__ B,
               float* __restrict__ out,
               const float* __restrict__ bias_r,
               const float* __restrict__ bias_i)
{
    __shared__ __nv_bfloat16 smA[2][GBM*GLDA];
    __shared__ __nv_bfloat16 smB[2][GBN*GLDA];

    const int tid = threadIdx.x;
    const int m0 = blockIdx.y * GBM;
    const int n0 = blockIdx.x * GBN;
    const int w = tid >> 5, l = tid & 31;
    const int wm = (w & 1) * 64;
    const int wn = (w >> 1) * 32;
    const int g = l >> 2, t = l & 3;

    // global loader mapping: 2 x uint4 (8 bf16) per tensor per thread
    const int lr = tid >> 2;          // 0..63
    const int lk = (tid & 3) << 3;    // 0,8,16,24

    const __nv_bfloat16* gA0 = A + (size_t)(m0 + lr) * GK + lk;
    const __nv_bfloat16* gA1 = gA0 + (size_t)64 * GK;
    const __nv_bfloat16* gB0 = B + (size_t)(n0 + lr) * GK + lk;
    const __nv_bfloat16* gB1 = gB0 + (size_t)64 * GK;

    float acc[4][4][4];
    #pragma unroll
    for (int i = 0; i < 4; i++)
        #pragma unroll
        for (int j = 0; j < 4; j++)
            #pragma unroll
            for (int v = 0; v < 4; v++) acc[i][j][v] = 0.f;

    // prologue: tile 0 -> buf 0
    uint4 ra0 = *(const uint4*)gA0;
    uint4 ra1 = *(const uint4*)gA1;
    uint4 rb0 = *(const uint4*)gB0;
    uint4 rb1 = *(const uint4*)gB1;
    *(uint4*)&smA[0][lr*GLDA + lk]        = ra0;
    *(uint4*)&smA[0][(lr + 64)*GLDA + lk] = ra1;
    *(uint4*)&smB[0][lr*GLDA + lk]        = rb0;
    *(uint4*)&smB[0][(lr + 64)*GLDA + lk] = rb1;
    __syncthreads();

    // per-lane ldmatrix offsets
    const int aRow = wm + (l & 15);
    const int aK   = (l >> 4) << 3;
    const int bRow = wn + (l & 7) + (((l >> 4) & 1) << 3);
    const int bK   = ((l >> 3) & 1) << 3;

    const int NK = GK / GBK;   // 192
    for (int kt = 0; kt < NK; kt++) {
        const int cur = kt & 1;
        if (kt + 1 < NK) {
            const size_t ko = (size_t)(kt + 1) * GBK;
            ra0 = *(const uint4*)(gA0 + ko);
            ra1 = *(const uint4*)(gA1 + ko);
            rb0 = *(const uint4*)(gB0 + ko);
            rb1 = *(const uint4*)(gB1 + ko);
        }
        const uint32_t aBase = (uint32_t)__cvta_generic_to_shared(&smA[cur][0]);
        const uint32_t bBase = (uint32_t)__cvta_generic_to_shared(&smB[cur][0]);
        #pragma unroll
        for (int ks = 0; ks < GBK; ks += 16) {
            uint32_t af[4][4], bfr[4][2];
            #pragma unroll
            for (int mt = 0; mt < 4; mt++) {
                const uint32_t ad = aBase +
                    (uint32_t)(((aRow + mt*16)*GLDA + ks + aK) * 2);
                ldsm_x4(af[mt][0], af[mt][1], af[mt][2], af[mt][3], ad);
            }
            #pragma unroll
            for (int np = 0; np < 2; np++) {
                const uint32_t bd = bBase +
                    (uint32_t)(((bRow + np*16)*GLDA + ks + bK) * 2);
                ldsm_x4(bfr[2*np][0], bfr[2*np][1], bfr[2*np+1][0], bfr[2*np+1][1], bd);
            }
            #pragma unroll
            for (int mt = 0; mt < 4; mt++)
                #pragma unroll
                for (int nt = 0; nt < 4; nt++)
                    mma_bf16(acc[mt][nt],
                             af[mt][0], af[mt][1], af[mt][2], af[mt][3],
                             bfr[nt][0], bfr[nt][1]);
        }
        if (kt + 1 < NK) {
            const int nxt = cur ^ 1;
            *(uint4*)&smA[nxt][lr*GLDA + lk]        = ra0;
            *(uint4*)&smA[nxt][(lr + 64)*GLDA + lk] = ra1;
            *(uint4*)&smB[nxt][lr*GLDA + lk]        = rb0;
            *(uint4*)&smB[nxt][(lr + 64)*GLDA + lk] = rb1;
            __syncthreads();
        }
    }

    // epilogue: write to per-1024-col buffers; optional bias (N<=2048 case)
    const bool hb = (bias_r != nullptr);
    #pragma unroll
    for (int mt = 0; mt < 4; mt++) {
        const int row0 = m0 + wm + mt*16 + g;
        #pragma unroll
        for (int nt = 0; nt < 4; nt++) {
            const int c = n0 + wn + nt*8 + 2*t;
            const size_t cb = (size_t)(c >> 10) * SSZ + (c & 1023);
            float b0 = 0.f, b1 = 0.f;
            if (hb) {
                const float* bp = (c & 1024) ? bias_i : bias_r;
                b0 = bp[c & 1023];
                b1 = bp[(c & 1023) + 1];
            }
            float2 v0 = make_float2(acc[mt][nt][0] + b0, acc[mt][nt][1] + b1);
            float2 v1 = make_float2(acc[mt][nt][2] + b0, acc[mt][nt][3] + b1);
            *(float2*)&out[cb + (size_t)row0 * 1024]       = v0;
            *(float2*)&out[cb + (size_t)(row0 + 8) * 1024] = v1;
        }
    }
}

// ---------------------------------------------------------------------------
// Flash attention, causal, complex scores: S = (Qr Kr^T + Qi Ki^T) * 0.125
// ---------------------------------------------------------------------------
#define LDK 68
#define FLASH_SMEM ((6*64*LDK + 64*64) * 4)

__device__ __forceinline__ float redmax16(float v) {
    v = fmaxf(v, __shfl_xor_sync(0xffffffffu, v, 1));
    v = fmaxf(v, __shfl_xor_sync(0xffffffffu, v, 2));
    v = fmaxf(v, __shfl_xor_sync(0xffffffffu, v, 4));
    v = fmaxf(v, __shfl_xor_sync(0xffffffffu, v, 8));
    return v;
}
__device__ __forceinline__ float redsum16(float v) {
    v += __shfl_xor_sync(0xffffffffu, v, 1);
    v += __shfl_xor_sync(0xffffffffu, v, 2);
    v += __shfl_xor_sync(0xffffffffu, v, 4);
    v += __shfl_xor_sync(0xffffffffu, v, 8);
    return v;
}

__global__ __launch_bounds__(256, 1)
void flash_kernel(const float* __restrict__ Qr, const float* __restrict__ Qi,
                  const float* __restrict__ Kr, const float* __restrict__ Ki,
                  const float* __restrict__ Vr, const float* __restrict__ Vi,
                  float* __restrict__ Or_, float* __restrict__ Oi_)
{
    extern __shared__ float sm[];
    float* Qs_r = sm;
    float* Qs_i = Qs_r + 64*LDK;
    float* Ks_r = Qs_i + 64*LDK;
    float* Ks_i = Ks_r + 64*LDK;
    float* Vt_r = Ks_i + 64*LDK;   // transposed: [dv][k]
    float* Vt_i = Vt_r + 64*LDK;
    float* Ps   = Vt_i + 64*LDK;   // [64][64]

    const int qt = blockIdx.x;
    const int h  = blockIdx.y;
    const int b  = blockIdx.z;
    const int q0 = qt * 64;
    const int tid = threadIdx.x;
    const int tx = tid & 15, ty = tid >> 4;
    const size_t base = ((size_t)b * LQ) * DQ + (size_t)h * HDQ;

    const int lrow = tid >> 4;          // 0..15
    const int fc   = (tid & 15) * 4;    // 0..60

    #pragma unroll
    for (int r4 = 0; r4 < 4; r4++) {
        const int row = lrow + 16*r4;
        const float4 qr = *(const float4*)(Qr + base + (size_t)(q0+row)*DQ + fc);
        const float4 qi = *(const float4*)(Qi + base + (size_t)(q0+row)*DQ + fc);
        *(float4*)&Qs_r[row*LDK + fc] = qr;
        *(float4*)&Qs_i[row*LDK + fc] = qi;
    }

    float m_i[4], l_i[4];
    float o_r[4][4], o_i[4][4];
    #pragma unroll
    for (int i = 0; i < 4; i++) {
        m_i[i] = -CUDART_INF_F; l_i[i] = 0.f;
        #pragma unroll
        for (int j = 0; j < 4; j++) { o_r[i][j] = 0.f; o_i[i][j] = 0.f; }
    }

    for (int kt = 0; kt <= qt; kt++) {
        const int k0 = kt * 64;
        __syncthreads();
        #pragma unroll
        for (int r4 = 0; r4 < 4; r4++) {
            const int row = lrow + 16*r4;
            const float4 kr = *(const float4*)(Kr + base + (size_t)(k0+row)*DQ + fc);
            const float4 ki = *(const float4*)(Ki + base + (size_t)(k0+row)*DQ + fc);
            *(float4*)&Ks_r[row*LDK + fc] = kr;
            *(float4*)&Ks_i[row*LDK + fc] = ki;
            const float4 vr = *(const float4*)(Vr + base + (size_t)(k0+row)*DQ + fc);
            const float4 vi = *(const float4*)(Vi + base + (size_t)(k0+row)*DQ + fc);
            Vt_r[(fc+0)*LDK + row] = vr.x; Vt_r[(fc+1)*LDK + row] = vr.y;
            Vt_r[(fc+2)*LDK + row] = vr.z; Vt_r[(fc+3)*LDK + row] = vr.w;
            Vt_i[(fc+0)*LDK + row] = vi.x; Vt_i[(fc+1)*LDK + row] = vi.y;
            Vt_i[(fc+2)*LDK + row] = vi.z; Vt_i[(fc+3)*LDK + row] = vi.w;
        }
        __syncthreads();

        float s_[4][4] = {};
        #pragma unroll
        for (int d4 = 0; d4 < 64; d4 += 4) {
            float4 q_r[4], q_i[4];
            #pragma unroll
            for (int i = 0; i < 4; i++) {
                q_r[i] = *(const float4*)&Qs_r[(ty + 16*i)*LDK + d4];
                q_i[i] = *(const float4*)&Qs_i[(ty + 16*i)*LDK + d4];
            }
            #pragma unroll
            for (int j = 0; j < 4; j++) {
                const float4 k_r = *(const float4*)&Ks_r[(tx + 16*j)*LDK + d4];
                const float4 k_i = *(const float4*)&Ks_i[(tx + 16*j)*LDK + d4];
                #pragma unroll
                for (int i = 0; i < 4; i++) {
                    float acc = s_[i][j];
                    acc = fmaf(q_r[i].x, k_r.x, acc);
                    acc = fmaf(q_r[i].y, k_r.y, acc);
                    acc = fmaf(q_r[i].z, k_r.z, acc);
                    acc = fmaf(q_r[i].w, k_r.w, acc);
                    acc = fmaf(q_i[i].x, k_i.x, acc);
                    acc = fmaf(q_i[i].y, k_i.y, acc);
                    acc = fmaf(q_i[i].z, k_i.z, acc);
                    acc = fmaf(q_i[i].w, k_i.w, acc);
                    s_[i][j] = acc;
                }
            }
        }

        const bool diag = (kt == qt);
        #pragma unroll
        for (int i = 0; i < 4; i++) {
            const int qrow = ty + 16*i;
            float rm = -CUDART_INF_F;
            #pragma unroll
            for (int j = 0; j < 4; j++) {
                float v = s_[i][j] * 0.125f;
                if (diag && (tx + 16*j) > qrow) v = -CUDART_INF_F;
                s_[i][j] = v;
                rm = fmaxf(rm, v);
            }
            rm = redmax16(rm);
            const float mnew = fmaxf(m_i[i], rm);
            const float corr = __expf(m_i[i] - mnew);
            m_i[i] = mnew;
            float rs = 0.f;
            #pragma unroll
            for (int j = 0; j < 4; j++) {
                const float p = __expf(s_[i][j] - mnew);
                Ps[qrow*64 + tx + 16*j] = p;
                rs += p;
            }
            rs = redsum16(rs);
            l_i[i] = l_i[i]*corr + rs;
            #pragma unroll
            for (int j = 0; j < 4; j++) { o_r[i][j] *= corr; o_i[i][j] *= corr; }
        }
        __syncthreads();

        #pragma unroll
        for (int k4 = 0; k4 < 64; k4 += 4) {
            float4 p4[4];
            #pragma unroll
            for (int i = 0; i < 4; i++)
                p4[i] = *(const float4*)&Ps[(ty + 16*i)*64 + k4];
            #pragma unroll
            for (int j = 0; j < 4; j++) {
                const float4 v_r = *(const float4*)&Vt_r[(tx + 16*j)*LDK + k4];
                const float4 v_i = *(const float4*)&Vt_i[(tx + 16*j)*LDK + k4];
                #pragma unroll
                for (int i = 0; i < 4; i++) {
                    float ar = o_r[i][j], ai = o_i[i][j];
                    ar = fmaf(p4[i].x, v_r.x, ar); ai = fmaf(p4[i].x, v_i.x, ai);
                    ar = fmaf(p4[i].y, v_r.y, ar); ai = fmaf(p4[i].y, v_i.y, ai);
                    ar = fmaf(p4[i].z, v_r.z, ar); ai = fmaf(p4[i].z, v_i.z, ai);
                    ar = fmaf(p4[i].w, v_r.w, ar); ai = fmaf(p4[i].w, v_i.w, ai);
                    o_r[i][j] = ar; o_i[i][j] = ai;
                }
            }
        }
    }

    #pragma unroll
    for (int i = 0; i < 4; i++) {
        const float inv = 1.0f / l_i[i];
        const int qrow = q0 + ty + 16*i;
        #pragma unroll
        for (int j = 0; j < 4; j++) {
            const size_t idx = base + (size_t)qrow*DQ + tx + 16*j;
            Or_[idx] = o_r[i][j] * inv;
            Oi_[idx] = o_i[i][j] * inv;
        }
    }
}

// ---------------------------------------------------------------------------
extern "C" void kernel_launch(void* const* d_in, const int* in_sizes, int n_in,
                              void* d_out, int out_size)
{
    const float* x_r  = (const float*)d_in[0];
    const float* x_i  = (const float*)d_in[1];
    const float* wq_r = (const float*)d_in[2];
    const float* wq_i = (const float*)d_in[3];
    const float* wk_r = (const float*)d_in[4];
    const float* wk_i = (const float*)d_in[5];
    const float* wv_r = (const float*)d_in[6];
    const float* wv_i = (const float*)d_in[7];
    const float* wo_r = (const float*)d_in[8];
    const float* wo_i = (const float*)d_in[9];
    const float* bo_r = (const float*)d_in[10];
    const float* bo_i = (const float*)d_in[11];

    float* scratch = nullptr;
    cudaGetSymbolAddress((void**)&scratch, g_buf);
    __nv_bfloat16* Ax = nullptr;
    cudaGetSymbolAddress((void**)&Ax, g_Ax);
    __nv_bfloat16* Bqkv = nullptr;
    cudaGetSymbolAddress((void**)&Bqkv, g_Bqkv);
    __nv_bfloat16* Ao = nullptr;
    cudaGetSymbolAddress((void**)&Ao, g_Ao);
    __nv_bfloat16* Bo = nullptr;
    cudaGetSymbolAddress((void**)&Bo, g_Bo);

    float* Qr  = scratch + 0*SSZ;
    float* Qi  = scratch + 1*SSZ;
    float* Kr  = scratch + 2*SSZ;
    float* Ki  = scratch + 3*SSZ;
    float* Vr  = scratch + 4*SSZ;
    float* Vi  = scratch + 5*SSZ;
    float* Or_ = scratch + 6*SSZ;
    float* Oi_ = scratch + 7*SSZ;

    float* yout = (float*)d_out;   // yr = [0,SSZ), yi = [SSZ, 2*SSZ)

    cudaFuncSetAttribute(flash_kernel,
                         cudaFuncAttributeMaxDynamicSharedMemorySize, FLASH_SMEM);

    // split-prep
    build_A_kernel<<<(MQ*DQ)/256, 256>>>(x_r, x_i, Ax);
    build_B_kernel<<<(DQ*DQ)/256, 256>>>(wq_r, wq_i, Bqkv);
    build_B_kernel<<<(DQ*DQ)/256, 256>>>(wk_r, wk_i, Bqkv + (size_t)2048*GK);
    build_B_kernel<<<(DQ*DQ)/256, 256>>>(wv_r, wv_i, Bqkv + (size_t)4096*GK);
    build_B_kernel<<<(DQ*DQ)/256, 256>>>(wo_r, wo_i, Bo);

    // fused QKV projection: [4096, 6144] = A[4096,6144] @ B[6144,6144]^T
    dim3 gq(6144/GBN, MQ/GBM);
    gemm_bf16<<<gq, 256>>>(Ax, Bqkv, scratch, nullptr, nullptr);

    // attention
    dim3 gf(LQ/64, HQ, BQ);
    flash_kernel<<<gf, 256, FLASH_SMEM>>>(Qr, Qi, Kr, Ki, Vr, Vi, Or_, Oi_);

    // output projection (+bias) straight into d_out
    build_A_kernel<<<(MQ*DQ)/256, 256>>>(Or_, Oi_, Ao);
    dim3 go(2048/GBN, MQ/GBM);
    gemm_bf16<<<go, 256>>>(Ao, Bo, yout, bo_r, bo_i);
}

// round 4
// speedup vs baseline: 1.6769x; 1.1513x over previous
#include <cuda_runtime.h>
#include <cuda_bf16.h>
#include <math.h>
#include <math_constants.h>
#include <stdint.h>

// Problem constants
#define BQ 2
#define LQ 2048
#define DQ 1024
#define HQ 16
#define HDQ 64
#define MQ (BQ*LQ)          // 4096 rows
#define SSZ ((size_t)MQ*DQ) // elements per [B,L,D] buffer
#define GK 6144             // concat K for projections

// fp32 scratch: Qr,Qi,Kr,Ki,Vr,Vi,Or,Oi
__device__ float g_buf[8*SSZ];                       // 128 MB
// bf16 split operands for projections
__device__ __nv_bfloat16 g_Ax[(size_t)MQ*GK];        // 48 MB
__device__ __nv_bfloat16 g_Bqkv[(size_t)6*1024*GK];  // 72 MB
__device__ __nv_bfloat16 g_Ao[(size_t)MQ*GK];        // 48 MB
__device__ __nv_bfloat16 g_Bo[(size_t)2*1024*GK];    // 24 MB
// bf16 flash operands
__device__ __nv_bfloat16 g_Qcat[(size_t)32*LQ*256];  // 33.5 MB
__device__ __nv_bfloat16 g_Kcat[(size_t)32*LQ*256];  // 33.5 MB
__device__ __nv_bfloat16 g_Vt[(size_t)32*4*64*LQ];   // 33.5 MB

// ---------------------------------------------------------------------------
// Projection split-prep kernels
// ---------------------------------------------------------------------------
__global__ void build_A_kernel(const float* __restrict__ xr,
                               const float* __restrict__ xi,
                               __nv_bfloat16* __restrict__ A)
{
    const int idx = blockIdx.x * blockDim.x + threadIdx.x;
    if (idx >= MQ*DQ) return;
    const int m = idx >> 10, k = idx & 1023;
    const float vr = xr[idx], vi = xi[idx];
    const __nv_bfloat16 hr = __float2bfloat16(vr);
    const __nv_bfloat16 lr = __float2bfloat16(vr - __bfloat162float(hr));
    const __nv_bfloat16 hi_ = __float2bfloat16(vi);
    const __nv_bfloat16 li_ = __float2bfloat16(vi - __bfloat162float(hi_));
    __nv_bfloat16* row = A + (size_t)m * GK;
    row[k]        = hr;
    row[1024 + k] = hi_;
    row[2048 + k] = hr;
    row[3072 + k] = hi_;
    row[4096 + k] = lr;
    row[5120 + k] = li_;
}

__global__ void build_B_kernel(const float* __restrict__ wr,
                               const float* __restrict__ wi,
                               __nv_bfloat16* __restrict__ Bdst)
{
    const int idx = blockIdx.x * blockDim.x + threadIdx.x;
    if (idx >= DQ*DQ) return;
    const int n = idx >> 10, k = idx & 1023;
    const float vr = wr[idx], vi = wi[idx];
    const __nv_bfloat16 hr  = __float2bfloat16(vr);
    const __nv_bfloat16 lr  = __float2bfloat16(vr - __bfloat162float(hr));
    const __nv_bfloat16 hi_ = __float2bfloat16(vi);
    const __nv_bfloat16 li_ = __float2bfloat16(vi - __bfloat162float(hi_));
    const float nvi = -vi;
    const __nv_bfloat16 hni = __float2bfloat16(nvi);
    const __nv_bfloat16 lni = __float2bfloat16(nvi - __bfloat162float(hni));

    __nv_bfloat16* rrow = Bdst + (size_t)n * GK;
    __nv_bfloat16* irow = Bdst + (size_t)(n + 1024) * GK;
    rrow[k]        = hr;   rrow[1024 + k] = hni;
    rrow[2048 + k] = lr;   rrow[3072 + k] = lni;
    rrow[4096 + k] = hr;   rrow[5120 + k] = hni;

    irow[k]        = hi_;  irow[1024 + k] = hr;
    irow[2048 + k] = li_;  irow[3072 + k] = lr;
    irow[4096 + k] = hi_;  irow[5120 + k] = hr;
}

// ---------------------------------------------------------------------------
// Flash prep: Qcat/Kcat [bh, l, 256] = [Xr_hi|Xi_hi|Xr_lo|Xi_lo] (64 each)
// ---------------------------------------------------------------------------
__global__ void qk_prep(const float* __restrict__ Qr, const float* __restrict__ Qi,
                        const float* __restrict__ Kr, const float* __restrict__ Ki,
                        __nv_bfloat16* __restrict__ Qcat,
                        __nv_bfloat16* __restrict__ Kcat)
{
    const int idx = blockIdx.x * blockDim.x + threadIdx.x;   // over 32*2048*64
    const int d  = idx & 63;
    const int l  = (idx >> 6) & 2047;
    const int bh = idx >> 17;
    const int b = bh >> 4, h = bh & 15;
    const size_t src = ((size_t)b*LQ + l)*DQ + h*64 + d;
    const size_t dst = ((size_t)bh*LQ + l)*256 + d;

    float qr = Qr[src], qi = Qi[src];
    __nv_bfloat16 qrh = __float2bfloat16(qr);
    __nv_bfloat16 qih = __float2bfloat16(qi);
    Qcat[dst]       = qrh;
    Qcat[dst + 64]  = qih;
    Qcat[dst + 128] = __float2bfloat16(qr - __bfloat162float(qrh));
    Qcat[dst + 192] = __float2bfloat16(qi - __bfloat162float(qih));

    float kr = Kr[src], ki = Ki[src];
    __nv_bfloat16 krh = __float2bfloat16(kr);
    __nv_bfloat16 kih = __float2bfloat16(ki);
    Kcat[dst]       = krh;
    Kcat[dst + 64]  = kih;
    Kcat[dst + 128] = __float2bfloat16(kr - __bfloat162float(krh));
    Kcat[dst + 192] = __float2bfloat16(ki - __bfloat162float(kih));
}

// V transpose prep: Vt[bh][vb][d][l], vb: 0=Vr_hi 1=Vi_hi 2=Vr_lo 3=Vi_lo
// FIX R4: smem row stride 68 (float4-aligned for all rows); locals 16B-aligned.
__global__ void v_prep(const float* __restrict__ Vr, const float* __restrict__ Vi,
                       __nv_bfloat16* __restrict__ Vt)
{
    __shared__ float tr[64][68], ti[64][68];
    const int bh = blockIdx.x >> 5;
    const int lt = blockIdx.x & 31;
    const int b = bh >> 4, h = bh & 15;
    const int tid = threadIdx.x;
    const int r = tid >> 2, cb = (tid & 3) * 16;

    const size_t src = ((size_t)b*LQ + lt*64 + r)*DQ + h*64 + cb;
    #pragma unroll
    for (int i = 0; i < 4; i++) {
        *(float4*)&tr[r][cb + 4*i] = *(const float4*)(Vr + src + 4*i);
        *(float4*)&ti[r][cb + 4*i] = *(const float4*)(Vi + src + 4*i);
    }
    __syncthreads();

    // write: d-row = r, l-cols = lt*64 + cb .. +15
    __align__(16) __nv_bfloat16 vrh[16], vih[16], vrl[16], vil[16];
    #pragma unroll
    for (int j = 0; j < 16; j++) {
        const float fr = tr[cb + j][r];
        const float fi = ti[cb + j][r];
        vrh[j] = __float2bfloat16(fr);
        vrl[j] = __float2bfloat16(fr - __bfloat162float(vrh[j]));
        vih[j] = __float2bfloat16(fi);
        vil[j] = __float2bfloat16(fi - __bfloat162float(vih[j]));
    }
    const size_t rowlen = LQ;
    const size_t base0 = (((size_t)bh*4 + 0)*64 + r)*rowlen + lt*64 + cb;
    const size_t base1 = (((size_t)bh*4 + 1)*64 + r)*rowlen + lt*64 + cb;
    const size_t base2 = (((size_t)bh*4 + 2)*64 + r)*rowlen + lt*64 + cb;
    const size_t base3 = (((size_t)bh*4 + 3)*64 + r)*rowlen + lt*64 + cb;
    #pragma unroll
    for (int i = 0; i < 2; i++) {
        ((uint4*)(Vt + base0))[i] = ((uint4*)vrh)[i];
        ((uint4*)(Vt + base1))[i] = ((uint4*)vih)[i];
        ((uint4*)(Vt + base2))[i] = ((uint4*)vrl)[i];
        ((uint4*)(Vt + base3))[i] = ((uint4*)vil)[i];
    }
}

// ---------------------------------------------------------------------------
// mma helpers
// ---------------------------------------------------------------------------
__device__ __forceinline__ void ldsm_x4(uint32_t& r0, uint32_t& r1,
                                        uint32_t& r2, uint32_t& r3, uint32_t addr)
{
    asm volatile("ldmatrix.sync.aligned.m8n8.x4.shared.b16 {%0,%1,%2,%3}, [%4];"
                 : "=r"(r0), "=r"(r1), "=r"(r2), "=r"(r3) : "r"(addr));
}

__device__ __forceinline__ void mma_bf16(float* c,
                                         uint32_t a0, uint32_t a1, uint32_t a2, uint32_t a3,
                                         uint32_t b0, uint32_t b1)
{
    asm volatile("mma.sync.aligned.m16n8k16.row.col.f32.bf16.bf16.f32 "
                 "{%0,%1,%2,%3},{%4,%5,%6,%7},{%8,%9},{%0,%1,%2,%3};"
                 : "+f"(c[0]), "+f"(c[1]), "+f"(c[2]), "+f"(c[3])
                 : "r"(a0), "r"(a1), "r"(a2), "r"(a3), "r"(b0), "r"(b1));
}

// ---------------------------------------------------------------------------
// bf16 tensor-core GEMM for projections
// ---------------------------------------------------------------------------
#define GBM 128
#define GBN 128
#define GBK 32
#define GLDA 40

__global__ __launch_bounds__(256, 1)
void gemm_bf16(const __nv_bfloat16* __restrict__ A,
               const __nv_bfloat16* __restrict__ B,
               float* __restrict__ out,
               const float* __restrict__ bias_r,
               const float* __restrict__ bias_i)
{
    __shared__ __nv_bfloat16 smA[2][GBM*GLDA];
    __shared__ __nv_bfloat16 smB[2][GBN*GLDA];

    const int tid = threadIdx.x;
    const int m0 = blockIdx.y * GBM;
    const int n0 = blockIdx.x * GBN;
    const int w = tid >> 5, l = tid & 31;
    const int wm = (w & 1) * 64;
    const int wn = (w >> 1) * 32;
    const int g = l >> 2, t = l & 3;

    const int lr = tid >> 2;
    const int lk = (tid & 3) << 3;

    const __nv_bfloat16* gA0 = A + (size_t)(m0 + lr) * GK + lk;
    const __nv_bfloat16* gA1 = gA0 + (size_t)64 * GK;
    const __nv_bfloat16* gB0 = B + (size_t)(n0 + lr) * GK + lk;
    const __nv_bfloat16* gB1 = gB0 + (size_t)64 * GK;

    float acc[4][4][4];
    #pragma unroll
    for (int i = 0; i < 4; i++)
        #pragma unroll
        for (int j = 0; j < 4; j++)
            #pragma unroll
            for (int v = 0; v < 4; v++) acc[i][j][v] = 0.f;

    uint4 ra0 = *(const uint4*)gA0;
    uint4 ra1 = *(const uint4*)gA1;
    uint4 rb0 = *(const uint4*)gB0;
    uint4 rb1 = *(const uint4*)gB1;
    *(uint4*)&smA[0][lr*GLDA + lk]        = ra0;
    *(uint4*)&smA[0][(lr + 64)*GLDA + lk] = ra1;
    *(uint4*)&smB[0][lr*GLDA + lk]        = rb0;
    *(uint4*)&smB[0][(lr + 64)*GLDA + lk] = rb1;
    __syncthreads();

    const int aRow = wm + (l & 15);
    const int aK   = (l >> 4) << 3;
    const int bRow = wn + (l & 7) + (((l >> 4) & 1) << 3);
    const int bK   = ((l >> 3) & 1) << 3;

    const int NK = GK / GBK;
    for (int kt = 0; kt < NK; kt++) {
        const int cur = kt & 1;
        if (kt + 1 < NK) {
            const size_t ko = (size_t)(kt + 1) * GBK;
            ra0 = *(const uint4*)(gA0 + ko);
            ra1 = *(const uint4*)(gA1 + ko);
            rb0 = *(const uint4*)(gB0 + ko);
            rb1 = *(const uint4*)(gB1 + ko);
        }
        const uint32_t aBase = (uint32_t)__cvta_generic_to_shared(&smA[cur][0]);
        const uint32_t bBase = (uint32_t)__cvta_generic_to_shared(&smB[cur][0]);
        #pragma unroll
        for (int ks = 0; ks < GBK; ks += 16) {
            uint32_t af[4][4], bfr[4][2];
            #pragma unroll
            for (int mt = 0; mt < 4; mt++) {
                const uint32_t ad = aBase +
                    (uint32_t)(((aRow + mt*16)*GLDA + ks + aK) * 2);
                ldsm_x4(af[mt][0], af[mt][1], af[mt][2], af[mt][3], ad);
            }
            #pragma unroll
            for (int np = 0; np < 2; np++) {
                const uint32_t bd = bBase +
                    (uint32_t)(((bRow + np*16)*GLDA + ks + bK) * 2);
                ldsm_x4(bfr[2*np][0], bfr[2*np][1], bfr[2*np+1][0], bfr[2*np+1][1], bd);
            }
            #pragma unroll
            for (int mt = 0; mt < 4; mt++)
                #pragma unroll
                for (int nt = 0; nt < 4; nt++)
                    mma_bf16(acc[mt][nt],
                             af[mt][0], af[mt][1], af[mt][2], af[mt][3],
                             bfr[nt][0], bfr[nt][1]);
        }
        if (kt + 1 < NK) {
            const int nxt = cur ^ 1;
            *(uint4*)&smA[nxt][lr*GLDA + lk]        = ra0;
            *(uint4*)&smA[nxt][(lr + 64)*GLDA + lk] = ra1;
            *(uint4*)&smB[nxt][lr*GLDA + lk]        = rb0;
            *(uint4*)&smB[nxt][(lr + 64)*GLDA + lk] = rb1;
            __syncthreads();
        }
    }

    const bool hb = (bias_r != nullptr);
    #pragma unroll
    for (int mt = 0; mt < 4; mt++) {
        const int row0 = m0 + wm + mt*16 + g;
        #pragma unroll
        for (int nt = 0; nt < 4; nt++) {
            const int c = n0 + wn + nt*8 + 2*t;
            const size_t cb = (size_t)(c >> 10) * SSZ + (c & 1023);
            float b0 = 0.f, b1 = 0.f;
            if (hb) {
                const float* bp = (c & 1024) ? bias_i : bias_r;
                b0 = bp[c & 1023];
                b1 = bp[(c & 1023) + 1];
            }
            float2 v0 = make_float2(acc[mt][nt][0] + b0, acc[mt][nt][1] + b1);
            float2 v1 = make_float2(acc[mt][nt][2] + b0, acc[mt][nt][3] + b1);
            *(float2*)&out[cb + (size_t)row0 * 1024]       = v0;
            *(float2*)&out[cb + (size_t)(row0 + 8) * 1024] = v1;
        }
    }
}

// ---------------------------------------------------------------------------
// Flash attention on tensor cores.
// Block = (qtile 64, h, b). 256 threads, 8 warps: wm=(w&3)*16, wn=(w>>2)*32.
// Scores: 3-pass split mma over cat layout. PV: 3-term split mma.
// ---------------------------------------------------------------------------
#define LDQ 264   // 256 + 8 pad (528B stride -> conflict-free ldmatrix)
#define LDV 72    // 64 + 8 pad (144B stride)
#define FL_SMEM ((64*LDQ*2 + 4*64*LDV + 2*64*LDV)*2 + 2*128*4)

__global__ __launch_bounds__(256, 1)
void flash_mma(const __nv_bfloat16* __restrict__ Qcat,
               const __nv_bfloat16* __restrict__ Kcat,
               const __nv_bfloat16* __restrict__ Vt,
               float* __restrict__ Or_, float* __restrict__ Oi_)
{
    extern __shared__ char smraw[];
    __nv_bfloat16* Qs = (__nv_bfloat16*)smraw;      // [64][LDQ]
    __nv_bfloat16* Ks = Qs + 64*LDQ;                // [64][LDQ]
    __nv_bfloat16* Vs = Ks + 64*LDQ;                // [4][64][LDV]
    __nv_bfloat16* Ph = Vs + 4*64*LDV;              // [64][LDV]
    __nv_bfloat16* Pl = Ph + 64*LDV;                // [64][LDV]
    float* rmax = (float*)(Pl + 64*LDV);            // [2][64]
    float* rsum = rmax + 128;                       // [2][64]

    const int qt = blockIdx.x, h = blockIdx.y, b = blockIdx.z;
    const int bh = b*HQ + h;
    const int q0 = qt * 64;
    const int tid = threadIdx.x;
    const int w = tid >> 5, l = tid & 31;
    const int wm = (w & 3) * 16;
    const int wn = (w >> 2) * 32;
    const int g = l >> 2, t4 = l & 3;
    const int half = w >> 2;

    // load Q tile once
    {
        const int r = tid >> 2, cb = (tid & 3) * 64;
        const __nv_bfloat16* src = Qcat + ((size_t)bh*LQ + q0 + r)*256 + cb;
        __nv_bfloat16* dst = Qs + r*LDQ + cb;
        #pragma unroll
        for (int i = 0; i < 8; i++) ((uint4*)dst)[i] = ((const uint4*)src)[i];
    }

    float m_[2] = {-CUDART_INF_F, -CUDART_INF_F};
    float lsum_[2] = {0.f, 0.f};
    float or_[4][4], oi_[4][4];
    #pragma unroll
    for (int nf = 0; nf < 4; nf++)
        #pragma unroll
        for (int v = 0; v < 4; v++) { or_[nf][v] = 0.f; oi_[nf][v] = 0.f; }

    const uint32_t qsB = (uint32_t)__cvta_generic_to_shared(Qs);
    const uint32_t ksB = (uint32_t)__cvta_generic_to_shared(Ks);
    const uint32_t vsB = (uint32_t)__cvta_generic_to_shared(Vs);
    const uint32_t phB = (uint32_t)__cvta_generic_to_shared(Ph);
    const uint32_t plB = (uint32_t)__cvta_generic_to_shared(Pl);

    const int aRow = wm + (l & 15);
    const int aK   = (l >> 4) << 3;
    const int bRow = wn + (l & 7) + (((l >> 4) & 1) << 3);
    const int bK   = ((l >> 3) & 1) << 3;
    const int pRow = wm + (l & 15);

    for (int kt = 0; kt <= qt; kt++) {
        const int k0 = kt * 64;
        __syncthreads();   // previous tile consumed
        // load K tile
        {
            const int r = tid >> 2, cb = (tid & 3) * 64;
            const __nv_bfloat16* src = Kcat + ((size_t)bh*LQ + k0 + r)*256 + cb;
            __nv_bfloat16* dst = Ks + r*LDQ + cb;
            #pragma unroll
            for (int i = 0; i < 8; i++) ((uint4*)dst)[i] = ((const uint4*)src)[i];
        }
        // load V tiles (4 buffers)
        {
            const int vb = tid >> 6, d = tid & 63;
            const __nv_bfloat16* src = Vt + (((size_t)bh*4 + vb)*64 + d)*LQ + k0;
            __nv_bfloat16* dst = Vs + (vb*64 + d)*LDV;
            #pragma unroll
            for (int i = 0; i < 8; i++) ((uint4*)dst)[i] = ((const uint4*)src)[i];
        }
        __syncthreads();

        // ---- scores: 3-pass split mma, K-dim 128 each ----
        float s_[4][4];
        #pragma unroll
        for (int nf = 0; nf < 4; nf++)
            #pragma unroll
            for (int v = 0; v < 4; v++) s_[nf][v] = 0.f;

        #pragma unroll
        for (int pass = 0; pass < 3; pass++) {
            const int qoff = (pass == 1) ? 128 : 0;
            const int koff = (pass == 2) ? 128 : 0;
            #pragma unroll
            for (int ks = 0; ks < 128; ks += 16) {
                uint32_t a0, a1, a2, a3;
                ldsm_x4(a0, a1, a2, a3,
                        qsB + (uint32_t)((aRow*LDQ + qoff + ks + aK) * 2));
                uint32_t bf_[4][2];
                #pragma unroll
                for (int np = 0; np < 2; np++) {
                    ldsm_x4(bf_[2*np][0], bf_[2*np][1], bf_[2*np+1][0], bf_[2*np+1][1],
                            ksB + (uint32_t)(((bRow + 16*np)*LDQ + koff + ks + bK) * 2));
                }
                #pragma unroll
                for (int nf = 0; nf < 4; nf++)
                    mma_bf16(s_[nf], a0, a1, a2, a3, bf_[nf][0], bf_[nf][1]);
            }
        }

        // ---- softmax ----
        const bool diag = (kt == qt);
        const int row0 = q0 + wm + g, row1 = row0 + 8;
        float pm0 = -CUDART_INF_F, pm1 = -CUDART_INF_F;
        #pragma unroll
        for (int nf = 0; nf < 4; nf++) {
            const int c0 = k0 + wn + nf*8 + t4*2;
            float v0 = s_[nf][0]*0.125f, v1 = s_[nf][1]*0.125f;
            float v2 = s_[nf][2]*0.125f, v3 = s_[nf][3]*0.125f;
            if (diag) {
                if (c0     > row0) v0 = -CUDART_INF_F;
                if (c0 + 1 > row0) v1 = -CUDART_INF_F;
                if (c0     > row1) v2 = -CUDART_INF_F;
                if (c0 + 1 > row1) v3 = -CUDART_INF_F;
            }
            s_[nf][0] = v0; s_[nf][1] = v1; s_[nf][2] = v2; s_[nf][3] = v3;
            pm0 = fmaxf(pm0, fmaxf(v0, v1));
            pm1 = fmaxf(pm1, fmaxf(v2, v3));
        }
        pm0 = fmaxf(pm0, __shfl_xor_sync(0xffffffffu, pm0, 1));
        pm0 = fmaxf(pm0, __shfl_xor_sync(0xffffffffu, pm0, 2));
        pm1 = fmaxf(pm1, __shfl_xor_sync(0xffffffffu, pm1, 1));
        pm1 = fmaxf(pm1, __shfl_xor_sync(0xffffffffu, pm1, 2));
        if (t4 == 0) {
            rmax[half*64 + wm + g]     = pm0;
            rmax[half*64 + wm + g + 8] = pm1;
        }
        __syncthreads();
        const float mn0 = fmaxf(m_[0], fmaxf(rmax[wm + g],     rmax[64 + wm + g]));
        const float mn1 = fmaxf(m_[1], fmaxf(rmax[wm + g + 8], rmax[64 + wm + g + 8]));
        const float cr0 = __expf(m_[0] - mn0);
        const float cr1 = __expf(m_[1] - mn1);
        m_[0] = mn0; m_[1] = mn1;

        float ps0 = 0.f, ps1 = 0.f;
        #pragma unroll
        for (int nf = 0; nf < 4; nf++) {
            const int c = wn + nf*8 + t4*2;
            const float p0 = __expf(s_[nf][0] - mn0);
            const float p1 = __expf(s_[nf][1] - mn0);
            const float p2 = __expf(s_[nf][2] - mn1);
            const float p3 = __expf(s_[nf][3] - mn1);
            ps0 += p0 + p1;
            ps1 += p2 + p3;
            __nv_bfloat162 h01, l01, h23, l23;
            h01.x = __float2bfloat16(p0);
            h01.y = __float2bfloat16(p1);
            l01.x = __float2bfloat16(p0 - __bfloat162float(h01.x));
            l01.y = __float2bfloat16(p1 - __bfloat162float(h01.y));
            h23.x = __float2bfloat16(p2);
            h23.y = __float2bfloat16(p3);
            l23.x = __float2bfloat16(p2 - __bfloat162float(h23.x));
            l23.y = __float2bfloat16(p3 - __bfloat162float(h23.y));
            *(__nv_bfloat162*)&Ph[(wm + g)*LDV + c]     = h01;
            *(__nv_bfloat162*)&Pl[(wm + g)*LDV + c]     = l01;
            *(__nv_bfloat162*)&Ph[(wm + g + 8)*LDV + c] = h23;
            *(__nv_bfloat162*)&Pl[(wm + g + 8)*LDV + c] = l23;
        }
        ps0 += __shfl_xor_sync(0xffffffffu, ps0, 1);
        ps0 += __shfl_xor_sync(0xffffffffu, ps0, 2);
        ps1 += __shfl_xor_sync(0xffffffffu, ps1, 1);
        ps1 += __shfl_xor_sync(0xffffffffu, ps1, 2);
        if (t4 == 0) {
            rsum[half*64 + wm + g]     = ps0;
            rsum[half*64 + wm + g + 8] = ps1;
        }
        __syncthreads();   // rsum + P visible
        lsum_[0] = lsum_[0]*cr0 + rsum[wm + g]     + rsum[64 + wm + g];
        lsum_[1] = lsum_[1]*cr1 + rsum[wm + g + 8] + rsum[64 + wm + g + 8];
        #pragma unroll
        for (int nf = 0; nf < 4; nf++) {
            or_[nf][0] *= cr0; or_[nf][1] *= cr0;
            or_[nf][2] *= cr1; or_[nf][3] *= cr1;
            oi_[nf][0] *= cr0; oi_[nf][1] *= cr0;
            oi_[nf][2] *= cr1; oi_[nf][3] *= cr1;
        }

        // ---- PV: O += Phi*Vhi + Phi*Vlo + Plo*Vhi (r and i) ----
        #pragma unroll
        for (int ks = 0; ks < 64; ks += 16) {
            uint32_t ah0, ah1, ah2, ah3, al0, al1, al2, al3;
            ldsm_x4(ah0, ah1, ah2, ah3, phB + (uint32_t)((pRow*LDV + ks + aK) * 2));
            ldsm_x4(al0, al1, al2, al3, plB + (uint32_t)((pRow*LDV + ks + aK) * 2));
            uint32_t vfr[4][4][2];   // [vb][nf][2]
            #pragma unroll
            for (int vb = 0; vb < 4; vb++) {
                #pragma unroll
                for (int np = 0; np < 2; np++) {
                    ldsm_x4(vfr[vb][2*np][0], vfr[vb][2*np][1],
                            vfr[vb][2*np+1][0], vfr[vb][2*np+1][1],
                            vsB + (uint32_t)(((vb*64 + bRow + 16*np)*LDV + ks + bK) * 2));
                }
            }
            #pragma unroll
            for (int nf = 0; nf < 4; nf++) {
                mma_bf16(or_[nf], ah0, ah1, ah2, ah3, vfr[0][nf][0], vfr[0][nf][1]);
                mma_bf16(or_[nf], ah0, ah1, ah2, ah3, vfr[2][nf][0], vfr[2][nf][1]);
                mma_bf16(or_[nf], al0, al1, al2, al3, vfr[0][nf][0], vfr[0][nf][1]);
                mma_bf16(oi_[nf], ah0, ah1, ah2, ah3, vfr[1][nf][0], vfr[1][nf][1]);
                mma_bf16(oi_[nf], ah0, ah1, ah2, ah3, vfr[3][nf][0], vfr[3][nf][1]);
                mma_bf16(oi_[nf], al0, al1, al2, al3, vfr[1][nf][0], vfr[1][nf][1]);
            }
        }
    }

    // epilogue: normalize, write fp32 [b, l, h, d]
    const float inv0 = 1.0f / lsum_[0];
    const float inv1 = 1.0f / lsum_[1];
    const size_t obase = ((size_t)b*LQ)*DQ + (size_t)h*HDQ;
    const int row0 = q0 + wm + g, row1 = row0 + 8;
    #pragma unroll
    for (int nf = 0; nf < 4; nf++) {
        const int c = wn + nf*8 + t4*2;
        *(float2*)&Or_[obase + (size_t)row0*DQ + c] =
            make_float2(or_[nf][0]*inv0, or_[nf][1]*inv0);
        *(float2*)&Or_[obase + (size_t)row1*DQ + c] =
            make_float2(or_[nf][2]*inv1, or_[nf][3]*inv1);
        *(float2*)&Oi_[obase + (size_t)row0*DQ + c] =
            make_float2(oi_[nf][0]*inv0, oi_[nf][1]*inv0);
        *(float2*)&Oi_[obase + (size_t)row1*DQ + c] =
            make_float2(oi_[nf][2]*inv1, oi_[nf][3]*inv1);
    }
}

// ---------------------------------------------------------------------------
extern "C" void kernel_launch(void* const* d_in, const int* in_sizes, int n_in,
                              void* d_out, int out_size)
{
    const float* x_r  = (const float*)d_in[0];
    const float* x_i  = (const float*)d_in[1];
    const float* wq_r = (const float*)d_in[2];
    const float* wq_i = (const float*)d_in[3];
    const float* wk_r = (const float*)d_in[4];
    const float* wk_i = (const float*)d_in[5];
    const float* wv_r = (const float*)d_in[6];
    const float* wv_i = (const float*)d_in[7];
    const float* wo_r = (const float*)d_in[8];
    const float* wo_i = (const float*)d_in[9];
    const float* bo_r = (const float*)d_in[10];
    const float* bo_i = (const float*)d_in[11];

    float* scratch = nullptr;
    cudaGetSymbolAddress((void**)&scratch, g_buf);
    __nv_bfloat16 *Ax, *Bqkv, *Ao, *Bo, *Qcat, *Kcat, *Vt;
    cudaGetSymbolAddress((void**)&Ax, g_Ax);
    cudaGetSymbolAddress((void**)&Bqkv, g_Bqkv);
    cudaGetSymbolAddress((void**)&Ao, g_Ao);
    cudaGetSymbolAddress((void**)&Bo, g_Bo);
    cudaGetSymbolAddress((void**)&Qcat, g_Qcat);
    cudaGetSymbolAddress((void**)&Kcat, g_Kcat);
    cudaGetSymbolAddress((void**)&Vt, g_Vt);

    float* Qr  = scratch + 0*SSZ;
    float* Qi  = scratch + 1*SSZ;
    float* Kr  = scratch + 2*SSZ;
    float* Ki  = scratch + 3*SSZ;
    float* Vr  = scratch + 4*SSZ;
    float* Vi  = scratch + 5*SSZ;
    float* Or_ = scratch + 6*SSZ;
    float* Oi_ = scratch + 7*SSZ;

    float* yout = (float*)d_out;

    cudaFuncSetAttribute(flash_mma,
                         cudaFuncAttributeMaxDynamicSharedMemorySize, FL_SMEM);

    // split-prep for projections
    build_A_kernel<<<(MQ*DQ)/256, 256>>>(x_r, x_i, Ax);
    build_B_kernel<<<(DQ*DQ)/256, 256>>>(wq_r, wq_i, Bqkv);
    build_B_kernel<<<(DQ*DQ)/256, 256>>>(wk_r, wk_i, Bqkv + (size_t)2048*GK);
    build_B_kernel<<<(DQ*DQ)/256, 256>>>(wv_r, wv_i, Bqkv + (size_t)4096*GK);
    build_B_kernel<<<(DQ*DQ)/256, 256>>>(wo_r, wo_i, Bo);

    // fused QKV projection
    dim3 gq(6144/GBN, MQ/GBM);
    gemm_bf16<<<gq, 256>>>(Ax, Bqkv, scratch, nullptr, nullptr);

    // flash prep
    qk_prep<<<(32*LQ*64)/256, 256>>>(Qr, Qi, Kr, Ki, Qcat, Kcat);
    v_prep<<<32*32, 256>>>(Vr, Vi, Vt);

    // attention on tensor cores
    dim3 gf(LQ/64, HQ, BQ);
    flash_mma<<<gf, 256, FL_SMEM>>>(Qcat, Kcat, Vt, Or_, Oi_);

    // output projection (+bias) straight into d_out
    build_A_kernel<<<(MQ*DQ)/256, 256>>>(Or_, Oi_, Ao);
    dim3 go(2048/GBN, MQ/GBM);
    gemm_bf16<<<go, 256>>>(Ao, Bo, yout, bo_r, bo_i);
}